// round 6
// baseline (speedup 1.0000x reference)
#include <cuda_runtime.h>
#include <cuda_fp16.h>
#include <cstdint>

#define A_N   8
#define B_N   65536
#define OBS_N 128
#define ACT_N 32
#define E_N   128
#define BT    128
#define NTILES (B_N / BT)

// scratch (__device__ globals: allowed)
__device__ __align__(16) __half g_e[(size_t)A_N * B_N * E_N];   // 128 MB
__device__ __align__(16) float  g_vsum[(size_t)B_N * E_N];      // 32 MB (fp32 for accuracy)

// ---------------- helpers ----------------
__device__ __forceinline__ uint32_t smem_u32(const void* p) {
    uint32_t r;
    asm("{ .reg .u64 t; cvta.to.shared.u64 t, %1; cvt.u32.u64 %0, t; }" : "=r"(r) : "l"(p));
    return r;
}
__device__ __forceinline__ uint32_t packh(float a, float b) {
    __half2 h = __floats2half2_rn(a, b);
    return *(uint32_t*)&h;
}
__device__ __forceinline__ float lrelu(float x) { return x > 0.f ? x : 0.01f * x; }

__device__ __forceinline__ void ldsm_x4(uint32_t* r, uint32_t addr) {
    asm volatile("ldmatrix.sync.aligned.m8n8.x4.shared.b16 {%0,%1,%2,%3}, [%4];"
        : "=r"(r[0]), "=r"(r[1]), "=r"(r[2]), "=r"(r[3]) : "r"(addr));
}
__device__ __forceinline__ void ldsm_x4t(uint32_t* r, uint32_t addr) {
    asm volatile("ldmatrix.sync.aligned.m8n8.x4.trans.shared.b16 {%0,%1,%2,%3}, [%4];"
        : "=r"(r[0]), "=r"(r[1]), "=r"(r[2]), "=r"(r[3]) : "r"(addr));
}
__device__ __forceinline__ void mma16816(float* d, const uint32_t* a, const uint32_t* b) {
    asm volatile("mma.sync.aligned.m16n8k16.row.col.f32.f16.f16.f32 "
        "{%0,%1,%2,%3}, {%4,%5,%6,%7}, {%8,%9}, {%0,%1,%2,%3};"
        : "+f"(d[0]), "+f"(d[1]), "+f"(d[2]), "+f"(d[3])
        : "r"(a[0]), "r"(a[1]), "r"(a[2]), "r"(a[3]), "r"(b[0]), "r"(b[1]));
}

// xor-swizzle 16B chunks within groups of 8 -> conflict-free ldmatrix
__device__ __forceinline__ int swz(int chunk, int row) {
    return (chunk & ~7) | ((chunk ^ row) & 7);
}

// Warp GEMM: C[128x128] tile; warp computes rows [warpM, warpM+32), cols [wn*64, +64).
template<int NSTEPS>
__device__ __forceinline__ void wgemm(uint32_t aBase, int aStride, int aChunk0,
                                      uint32_t bBase,
                                      int warpM, int wn, int lane,
                                      float acc[16][4])
{
    const int lr = lane & 15, lh = lane >> 4;
    #pragma unroll
    for (int ks = 0; ks < NSTEPS; ks++) {
        uint32_t afr[2][4];
        #pragma unroll
        for (int mi = 0; mi < 2; mi++) {
            int row = warpM + mi * 16 + lr;
            int ch  = aChunk0 + 2 * ks + lh;
            ldsm_x4(afr[mi], aBase + row * aStride + swz(ch, row) * 16);
        }
        uint32_t bfr[4][4];
        #pragma unroll
        for (int nj = 0; nj < 4; nj++) {
            int k  = ks * 16 + lr;
            int ch = wn * 8 + nj * 2 + lh;
            ldsm_x4t(bfr[nj], bBase + k * 256 + swz(ch, k) * 16);
        }
        #pragma unroll
        for (int mi = 0; mi < 2; mi++)
            #pragma unroll
            for (int nj = 0; nj < 4; nj++) {
                mma16816(acc[mi * 8 + nj * 2],     afr[mi], &bfr[nj][0]);
                mma16816(acc[mi * 8 + nj * 2 + 1], afr[mi], &bfr[nj][2]);
            }
    }
}

#define ZERO_ACC(acc) do { \
    _Pragma("unroll") for (int _i = 0; _i < 16; _i++) \
    _Pragma("unroll") for (int _j = 0; _j < 4; _j++) (acc)[_i][_j] = 0.f; \
} while (0)

__device__ __forceinline__ uint4 cvt8(const float* p) {
    float4 f0 = ((const float4*)p)[0];
    float4 f1 = ((const float4*)p)[1];
    return make_uint4(packh(f0.x, f0.y), packh(f0.z, f0.w),
                      packh(f1.x, f1.y), packh(f1.z, f1.w));
}

// ---------------- K1 smem layout ----------------
#define K1_XH   0
#define K1_WG   (K1_XH + 49152)
#define K1_WV   (K1_WG + 40960)
#define K1_BG   (K1_WV + 32768)
#define K1_BV   (K1_BG + 512)
#define K1_SMEM (K1_BV + 512)     // 123904

__global__ void __launch_bounds__(256, 1) k1_kernel(
    const float* __restrict__ obs, const float* __restrict__ act,
    const float* __restrict__ Wg,  const float* __restrict__ bg,
    const float* __restrict__ Wv,  const float* __restrict__ bv)
{
    extern __shared__ char smem[];
    const uint32_t sb = smem_u32(smem);
    const int tid = threadIdx.x, wid = tid >> 5, lane = tid & 31;
    const int warpM = (wid >> 1) * 32, wn = wid & 1;
    const int b0 = blockIdx.x * BT;

    float* sbg = (float*)(smem + K1_BG);
    float* sbv = (float*)(smem + K1_BV);

    // persistent: WV B-tile: B[k=e][n=h*32+d] = Wv[h][e][d]
    for (int it = 0; it < 8; it++) {
        int idx = tid + it * 256;
        int k = idx >> 4, c = idx & 15;
        const float* p = Wv + (size_t)(c >> 2) * E_N * 32 + (size_t)k * 32 + (c & 3) * 8;
        *(uint4*)(smem + K1_WV + k * 256 + swz(c, k) * 16) = cvt8(p);
    }
    if (tid < 128) sbv[tid] = bv[tid];

    float vsum[16][4];
    ZERO_ACC(vsum);

    for (int a = 0; a < A_N; a++) {
        // ---- load x tile (obs||act) fp16 swizzled; Wg B-tile; bg ----
        for (int it = 0; it < 10; it++) {
            int idx = tid + it * 256;          // 128*20 chunks
            int r = idx / 20, c = idx % 20;
            const float* p = (c < 16)
                ? obs + ((size_t)a * B_N + b0 + r) * OBS_N + c * 8
                : act + ((size_t)a * B_N + b0 + r) * ACT_N + (c - 16) * 8;
            *(uint4*)(smem + K1_XH + r * 384 + swz(c, r) * 16) = cvt8(p);
        }
        for (int it = 0; it < 10; it++) {
            int idx = tid + it * 256;          // 160*16 chunks
            int k = idx >> 4, c = idx & 15;
            const float* p = Wg + (size_t)a * 160 * E_N + (size_t)k * E_N + c * 8;
            *(uint4*)(smem + K1_WG + k * 256 + swz(c, k) * 16) = cvt8(p);
        }
        if (tid < 128) sbg[tid] = bg[a * E_N + tid];
        __syncthreads();

        // ---- GEMM1: e_pre = x @ Wg (K=160) ----
        float acc[16][4];
        ZERO_ACC(acc);
        wgemm<10>(sb + K1_XH, 384, 0, sb + K1_WG, warpM, wn, lane, acc);
        __syncthreads();   // sibling warp reads same A rows: finish before in-place rewrite

        // ---- epilogue1: e = lrelu(.+bg) -> fp16 in-place (chunks 0..15, own rows/cols) ----
        #pragma unroll
        for (int mi = 0; mi < 2; mi++)
            #pragma unroll
            for (int ni = 0; ni < 8; ni++) {
                int r0 = warpM + mi * 16 + (lane >> 2);
                int c0 = wn * 64 + ni * 8 + (lane & 3) * 2;
                float* f = acc[mi * 8 + ni];
                uint32_t lo = packh(lrelu(f[0] + sbg[c0]), lrelu(f[1] + sbg[c0 + 1]));
                uint32_t hi = packh(lrelu(f[2] + sbg[c0]), lrelu(f[3] + sbg[c0 + 1]));
                *(uint32_t*)(smem + K1_XH + r0 * 384 + swz(c0 >> 3, r0) * 16 + (c0 & 7) * 2) = lo;
                int r1 = r0 + 8;
                *(uint32_t*)(smem + K1_XH + r1 * 384 + swz(c0 >> 3, r1) * 16 + (c0 & 7) * 2) = hi;
            }
        __syncthreads();

        // ---- e -> gmem (coalesced uint4) ----
        {
            __half* eg = g_e + ((size_t)a * B_N + b0) * E_N;
            for (int it = 0; it < 8; it++) {
                int idx = tid + it * 256;
                int r = idx >> 4, c = idx & 15;
                uint4 v = *(const uint4*)(smem + K1_XH + r * 384 + swz(c, r) * 16);
                *(uint4*)(eg + (size_t)r * E_N + c * 8) = v;
            }
        }

        // ---- GEMM2: P = e @ Wv (K=128); Vsum += lrelu(P + bv) ----
        ZERO_ACC(acc);
        wgemm<8>(sb + K1_XH, 384, 0, sb + K1_WV, warpM, wn, lane, acc);
        #pragma unroll
        for (int mi = 0; mi < 2; mi++)
            #pragma unroll
            for (int ni = 0; ni < 8; ni++) {
                int c0 = wn * 64 + ni * 8 + (lane & 3) * 2;
                float* f = acc[mi * 8 + ni];
                float* v = vsum[mi * 8 + ni];
                v[0] += lrelu(f[0] + sbv[c0]);
                v[1] += lrelu(f[1] + sbv[c0 + 1]);
                v[2] += lrelu(f[2] + sbv[c0]);
                v[3] += lrelu(f[3] + sbv[c0 + 1]);
            }
        __syncthreads();   // protect XH/WG overwrite next agent
    }

    // ---- Vsum -> gmem fp32 ----
    #pragma unroll
    for (int mi = 0; mi < 2; mi++)
        #pragma unroll
        for (int ni = 0; ni < 8; ni++) {
            int r0 = warpM + mi * 16 + (lane >> 2);
            int c0 = wn * 64 + ni * 8 + (lane & 3) * 2;
            float* v = vsum[mi * 8 + ni];
            *(float2*)(g_vsum + (size_t)(b0 + r0) * E_N + c0)     = make_float2(v[0], v[1]);
            *(float2*)(g_vsum + (size_t)(b0 + r0 + 8) * E_N + c0) = make_float2(v[2], v[3]);
        }
}

// ---------------- K2 smem layout ----------------
#define K2_XI   0
#define K2_WF1  (K2_XI  + 65536)
#define K2_WV   (K2_WF1 + 65536)
#define K2_BV   (K2_WV  + 32768)
#define K2_BF1  (K2_BV  + 512)
#define K2_WF2  (K2_BF1 + 512)
#define K2_QP   (K2_WF2 + 512)
#define K2_SMEM (K2_QP  + 1024)   // 166400

// agent-outer mapping: blockIdx.x = a*64 + g; CTA loads Wf1[a] ONCE, sweeps 8 tiles.
#define K2_GROUPS 64
#define K2_TILES_PER_CTA (NTILES / K2_GROUPS)   // 8

__global__ void __launch_bounds__(256, 1) k2_kernel(
    const float* __restrict__ Wv,  const float* __restrict__ bv,
    const float* __restrict__ Wf1, const float* __restrict__ bf1,
    const float* __restrict__ Wf2, const float* __restrict__ bf2,
    float* __restrict__ out)
{
    extern __shared__ char smem[];
    const uint32_t sb = smem_u32(smem);
    const int tid = threadIdx.x, wid = tid >> 5, lane = tid & 31;
    const int warpM = (wid >> 1) * 32, wn = wid & 1;
    const int a = blockIdx.x >> 6;           // agent
    const int grp = blockIdx.x & 63;         // tile group

    float* sbv  = (float*)(smem + K2_BV);
    float* sbf1 = (float*)(smem + K2_BF1);
    float* swf2 = (float*)(smem + K2_WF2);
    float* qp   = (float*)(smem + K2_QP);

    // one-time loads: WV B-tile, Wf1[a] B-tile, biases
    for (int it = 0; it < 8; it++) {
        int idx = tid + it * 256;
        int k = idx >> 4, c = idx & 15;
        const float* p = Wv + (size_t)(c >> 2) * E_N * 32 + (size_t)k * 32 + (c & 3) * 8;
        *(uint4*)(smem + K2_WV + k * 256 + swz(c, k) * 16) = cvt8(p);
    }
    for (int it = 0; it < 16; it++) {
        int idx = tid + it * 256;              // 256*16 chunks
        int k = idx >> 4, c = idx & 15;
        const float* p = Wf1 + (size_t)a * 256 * E_N + (size_t)k * E_N + c * 8;
        *(uint4*)(smem + K2_WF1 + k * 256 + swz(c, k) * 16) = cvt8(p);
    }
    if (tid < 128) {
        sbv[tid]  = bv[tid];
        sbf1[tid] = bf1[a * E_N + tid];
        swf2[tid] = Wf2[a * E_N + tid];
    }
    const float bf2a = bf2[a];
    __syncthreads();

    for (int ti = 0; ti < K2_TILES_PER_CTA; ti++) {
        const int b0 = (grp * K2_TILES_PER_CTA + ti) * BT;

        // ---- load e tile -> XI chunks 16..31 ----
        {
            const __half* eg = g_e + ((size_t)a * B_N + b0) * E_N;
            for (int it = 0; it < 8; it++) {
                int idx = tid + it * 256;
                int r = idx >> 4, c = idx & 15;
                uint4 v = *(const uint4*)(eg + (size_t)r * E_N + c * 8);
                *(uint4*)(smem + K2_XI + r * 512 + swz(16 + c, r) * 16) = v;
            }
        }
        __syncthreads();

        // ---- GEMM-V: P = e @ Wv (bit-identical to K1's GEMM2) ----
        float acc[16][4];
        ZERO_ACC(acc);
        wgemm<8>(sb + K2_XI, 512, 16, sb + K2_WV, warpM, wn, lane, acc);

        // ---- epilogue: xi = Vsum - lrelu(P + bv) -> fp16 chunks 0..15
        //      (writes disjoint from GEMM-V's reads of chunks 16..31) ----
        #pragma unroll
        for (int mi = 0; mi < 2; mi++)
            #pragma unroll
            for (int ni = 0; ni < 8; ni++) {
                int r0 = warpM + mi * 16 + (lane >> 2);
                int c0 = wn * 64 + ni * 8 + (lane & 3) * 2;
                float* f = acc[mi * 8 + ni];
                float2 v0 = *(const float2*)(g_vsum + (size_t)(b0 + r0) * E_N + c0);
                float2 v1 = *(const float2*)(g_vsum + (size_t)(b0 + r0 + 8) * E_N + c0);
                uint32_t lo = packh(v0.x - lrelu(f[0] + sbv[c0]), v0.y - lrelu(f[1] + sbv[c0 + 1]));
                uint32_t hi = packh(v1.x - lrelu(f[2] + sbv[c0]), v1.y - lrelu(f[3] + sbv[c0 + 1]));
                *(uint32_t*)(smem + K2_XI + r0 * 512 + swz(c0 >> 3, r0) * 16 + (c0 & 7) * 2) = lo;
                int r1 = r0 + 8;
                *(uint32_t*)(smem + K2_XI + r1 * 512 + swz(c0 >> 3, r1) * 16 + (c0 & 7) * 2) = hi;
            }
        __syncthreads();   // GEMM-f1 reads sibling warp's xi columns

        // ---- GEMM-f1: H = [xi | e] @ Wf1 (K=256) ----
        ZERO_ACC(acc);
        wgemm<16>(sb + K2_XI, 512, 0, sb + K2_WF1, warpM, wn, lane, acc);

        // ---- epilogue: qv = lrelu(H + bf1) . wf2 + bf2 (fp32) ----
        {
            float pr[2][2] = {{0.f, 0.f}, {0.f, 0.f}};
            #pragma unroll
            for (int mi = 0; mi < 2; mi++)
                #pragma unroll
                for (int ni = 0; ni < 8; ni++) {
                    int c0 = wn * 64 + ni * 8 + (lane & 3) * 2;
                    float* f = acc[mi * 8 + ni];
                    pr[mi][0] += lrelu(f[0] + sbf1[c0]) * swf2[c0]
                               + lrelu(f[1] + sbf1[c0 + 1]) * swf2[c0 + 1];
                    pr[mi][1] += lrelu(f[2] + sbf1[c0]) * swf2[c0]
                               + lrelu(f[3] + sbf1[c0 + 1]) * swf2[c0 + 1];
                }
            #pragma unroll
            for (int off = 1; off <= 2; off <<= 1) {
                #pragma unroll
                for (int mi = 0; mi < 2; mi++) {
                    pr[mi][0] += __shfl_xor_sync(0xFFFFFFFF, pr[mi][0], off);
                    pr[mi][1] += __shfl_xor_sync(0xFFFFFFFF, pr[mi][1], off);
                }
            }
            if ((lane & 3) == 0) {
                #pragma unroll
                for (int mi = 0; mi < 2; mi++) {
                    int r0 = warpM + mi * 16 + (lane >> 2);
                    qp[r0 * 2 + wn]       = pr[mi][0];
                    qp[(r0 + 8) * 2 + wn] = pr[mi][1];
                }
            }
        }
        __syncthreads();
        if (tid < 128)
            out[(size_t)a * B_N + b0 + tid] = qp[tid * 2] + qp[tid * 2 + 1] + bf2a;
        __syncthreads();   // protect XI/qp overwrite next tile
    }
}

extern "C" void kernel_launch(void* const* d_in, const int* in_sizes, int n_in,
                              void* d_out, int out_size) {
    const float* obs = (const float*)d_in[0];
    const float* act = (const float*)d_in[1];
    const float* Wg  = (const float*)d_in[2];
    const float* bg  = (const float*)d_in[3];
    // d_in[4] = Wq, d_in[5] = Wk : dead code (softmax over singleton axis -> alpha == 1)
    const float* Wv  = (const float*)d_in[6];
    const float* bv  = (const float*)d_in[7];
    const float* Wf1 = (const float*)d_in[8];
    const float* bf1 = (const float*)d_in[9];
    const float* Wf2 = (const float*)d_in[10];
    const float* bf2 = (const float*)d_in[11];
    float* out = (float*)d_out;

    cudaFuncSetAttribute(k1_kernel, cudaFuncAttributeMaxDynamicSharedMemorySize, K1_SMEM);
    cudaFuncSetAttribute(k2_kernel, cudaFuncAttributeMaxDynamicSharedMemorySize, K2_SMEM);

    k1_kernel<<<NTILES, 256, K1_SMEM>>>(obs, act, Wg, bg, Wv, bv);
    k2_kernel<<<A_N * K2_GROUPS, 256, K2_SMEM>>>(Wv, bv, Wf1, bf1, Wf2, bf2, out);
}

// round 7
// speedup vs baseline: 1.6147x; 1.6147x over previous
#include <cuda_runtime.h>
#include <cuda_fp16.h>
#include <cstdint>

#define A_N   8
#define B_N   65536
#define OBS_N 128
#define ACT_N 32
#define E_N   128
#define BT    128
#define NTILES (B_N / BT)

// scratch (__device__ globals: allowed)
__device__ __align__(16) __half g_e[(size_t)A_N * B_N * E_N];    // 128 MB
__device__ __align__(16) __half g_v[(size_t)A_N * B_N * E_N];    // 128 MB
__device__ __align__(16) float  g_vsum[(size_t)B_N * E_N];       // 32 MB

// ---------------- helpers ----------------
__device__ __forceinline__ uint32_t smem_u32(const void* p) {
    uint32_t r;
    asm("{ .reg .u64 t; cvta.to.shared.u64 t, %1; cvt.u32.u64 %0, t; }" : "=r"(r) : "l"(p));
    return r;
}
__device__ __forceinline__ uint32_t packh(float a, float b) {
    __half2 h = __floats2half2_rn(a, b);
    return *(uint32_t*)&h;
}
__device__ __forceinline__ float lrelu(float x) { return x > 0.f ? x : 0.01f * x; }

__device__ __forceinline__ void ldsm_x4(uint32_t* r, uint32_t addr) {
    asm volatile("ldmatrix.sync.aligned.m8n8.x4.shared.b16 {%0,%1,%2,%3}, [%4];"
        : "=r"(r[0]), "=r"(r[1]), "=r"(r[2]), "=r"(r[3]) : "r"(addr));
}
__device__ __forceinline__ void ldsm_x4t(uint32_t* r, uint32_t addr) {
    asm volatile("ldmatrix.sync.aligned.m8n8.x4.trans.shared.b16 {%0,%1,%2,%3}, [%4];"
        : "=r"(r[0]), "=r"(r[1]), "=r"(r[2]), "=r"(r[3]) : "r"(addr));
}
__device__ __forceinline__ void mma16816(float* d, const uint32_t* a, const uint32_t* b) {
    asm volatile("mma.sync.aligned.m16n8k16.row.col.f32.f16.f16.f32 "
        "{%0,%1,%2,%3}, {%4,%5,%6,%7}, {%8,%9}, {%0,%1,%2,%3};"
        : "+f"(d[0]), "+f"(d[1]), "+f"(d[2]), "+f"(d[3])
        : "r"(a[0]), "r"(a[1]), "r"(a[2]), "r"(a[3]), "r"(b[0]), "r"(b[1]));
}

// xor-swizzle 16B chunks within groups of 8 -> conflict-free ldmatrix
__device__ __forceinline__ int swz(int chunk, int row) {
    return (chunk & ~7) | ((chunk ^ row) & 7);
}

// Warp GEMM, 16-warp version: C[128x128]; warp (wm, wn) computes
// rows [wm*32, +32), cols [wn*32, +32). acc[8][4], index mi*4 + nj*2 + h.
template<int NSTEPS>
__device__ __forceinline__ void wgemm(uint32_t aBase, int aStride, int aChunk0,
                                      uint32_t bBase,
                                      int warpM, int wn, int lane,
                                      float acc[8][4])
{
    const int lr = lane & 15, lh = lane >> 4;
    #pragma unroll
    for (int ks = 0; ks < NSTEPS; ks++) {
        uint32_t afr[2][4];
        #pragma unroll
        for (int mi = 0; mi < 2; mi++) {
            int row = warpM + mi * 16 + lr;
            int ch  = aChunk0 + 2 * ks + lh;
            ldsm_x4(afr[mi], aBase + row * aStride + swz(ch, row) * 16);
        }
        uint32_t bfr[2][4];
        #pragma unroll
        for (int nj = 0; nj < 2; nj++) {
            int k  = ks * 16 + lr;
            int ch = wn * 4 + nj * 2 + lh;
            ldsm_x4t(bfr[nj], bBase + k * 256 + swz(ch, k) * 16);
        }
        #pragma unroll
        for (int mi = 0; mi < 2; mi++)
            #pragma unroll
            for (int nj = 0; nj < 2; nj++) {
                mma16816(acc[mi * 4 + nj * 2],     afr[mi], &bfr[nj][0]);
                mma16816(acc[mi * 4 + nj * 2 + 1], afr[mi], &bfr[nj][2]);
            }
    }
}

#define ZERO_ACC8(acc) do { \
    _Pragma("unroll") for (int _i = 0; _i < 8; _i++) \
    _Pragma("unroll") for (int _j = 0; _j < 4; _j++) (acc)[_i][_j] = 0.f; \
} while (0)

__device__ __forceinline__ uint4 cvt8(const float* p) {
    float4 f0 = ((const float4*)p)[0];
    float4 f1 = ((const float4*)p)[1];
    return make_uint4(packh(f0.x, f0.y), packh(f0.z, f0.w),
                      packh(f1.x, f1.y), packh(f1.z, f1.w));
}

#define NTHREADS 512

// ---------------- K1 smem layout ----------------
#define K1_XH   0
#define K1_WG   (K1_XH + 49152)
#define K1_WV   (K1_WG + 40960)
#define K1_BG   (K1_WV + 32768)
#define K1_BV   (K1_BG + 512)
#define K1_SMEM (K1_BV + 512)     // 123904

__global__ void __launch_bounds__(NTHREADS, 1) k1_kernel(
    const float* __restrict__ obs, const float* __restrict__ act,
    const float* __restrict__ Wg,  const float* __restrict__ bg,
    const float* __restrict__ Wv,  const float* __restrict__ bv)
{
    extern __shared__ char smem[];
    const uint32_t sb = smem_u32(smem);
    const int tid = threadIdx.x, wid = tid >> 5, lane = tid & 31;
    const int warpM = (wid >> 2) * 32, wn = wid & 3;
    const int b0 = blockIdx.x * BT;

    float* sbg = (float*)(smem + K1_BG);
    float* sbv = (float*)(smem + K1_BV);

    // persistent: WV B-tile: B[k=e][n=h*32+d] = Wv[h][e][d]
    for (int it = 0; it < 4; it++) {
        int idx = tid + it * NTHREADS;          // 128*16 chunks
        int k = idx >> 4, c = idx & 15;
        const float* p = Wv + (size_t)(c >> 2) * E_N * 32 + (size_t)k * 32 + (c & 3) * 8;
        *(uint4*)(smem + K1_WV + k * 256 + swz(c, k) * 16) = cvt8(p);
    }
    if (tid < 128) sbv[tid] = bv[tid];

    float vsum[8][4];
    ZERO_ACC8(vsum);

    for (int a = 0; a < A_N; a++) {
        // ---- load x tile (obs||act) fp16 swizzled; Wg B-tile; bg ----
        for (int it = 0; it < 5; it++) {
            int idx = tid + it * NTHREADS;      // 128*20 chunks
            int r = idx / 20, c = idx % 20;
            const float* p = (c < 16)
                ? obs + ((size_t)a * B_N + b0 + r) * OBS_N + c * 8
                : act + ((size_t)a * B_N + b0 + r) * ACT_N + (c - 16) * 8;
            *(uint4*)(smem + K1_XH + r * 384 + swz(c, r) * 16) = cvt8(p);
        }
        for (int it = 0; it < 5; it++) {
            int idx = tid + it * NTHREADS;      // 160*16 chunks
            int k = idx >> 4, c = idx & 15;
            const float* p = Wg + (size_t)a * 160 * E_N + (size_t)k * E_N + c * 8;
            *(uint4*)(smem + K1_WG + k * 256 + swz(c, k) * 16) = cvt8(p);
        }
        if (tid < 128) sbg[tid] = bg[a * E_N + tid];
        __syncthreads();

        // ---- GEMM1: e_pre = x @ Wg (K=160) ----
        float acc[8][4];
        ZERO_ACC8(acc);
        wgemm<10>(sb + K1_XH, 384, 0, sb + K1_WG, warpM, wn, lane, acc);
        __syncthreads();   // all warps read all A rows: finish before in-place rewrite

        // ---- epilogue1: e = lrelu(.+bg) -> fp16 in-place (chunks 0..15, own rows/cols) ----
        #pragma unroll
        for (int i = 0; i < 8; i++) {
            int r0 = warpM + (i >> 2) * 16 + (lane >> 2);
            int c0 = wn * 32 + (i & 3) * 8 + (lane & 3) * 2;
            float* f = acc[i];
            uint32_t lo = packh(lrelu(f[0] + sbg[c0]), lrelu(f[1] + sbg[c0 + 1]));
            uint32_t hi = packh(lrelu(f[2] + sbg[c0]), lrelu(f[3] + sbg[c0 + 1]));
            *(uint32_t*)(smem + K1_XH + r0 * 384 + swz(c0 >> 3, r0) * 16 + (c0 & 7) * 2) = lo;
            int r1 = r0 + 8;
            *(uint32_t*)(smem + K1_XH + r1 * 384 + swz(c0 >> 3, r1) * 16 + (c0 & 7) * 2) = hi;
        }
        __syncthreads();

        // ---- e -> gmem (coalesced uint4) ----
        {
            __half* eg = g_e + ((size_t)a * B_N + b0) * E_N;
            for (int it = 0; it < 4; it++) {
                int idx = tid + it * NTHREADS;
                int r = idx >> 4, c = idx & 15;
                uint4 v = *(const uint4*)(smem + K1_XH + r * 384 + swz(c, r) * 16);
                *(uint4*)(eg + (size_t)r * E_N + c * 8) = v;
            }
        }

        // ---- GEMM2: P = e @ Wv (K=128); V = lrelu(P+bv); Vsum += V; V -> g_v ----
        ZERO_ACC8(acc);
        wgemm<8>(sb + K1_XH, 384, 0, sb + K1_WV, warpM, wn, lane, acc);
        {
            __half* vg = g_v + ((size_t)a * B_N + b0) * E_N;
            #pragma unroll
            for (int i = 0; i < 8; i++) {
                int r0 = warpM + (i >> 2) * 16 + (lane >> 2);
                int c0 = wn * 32 + (i & 3) * 8 + (lane & 3) * 2;
                float* f = acc[i];
                float* v = vsum[i];
                float t0 = lrelu(f[0] + sbv[c0]);
                float t1 = lrelu(f[1] + sbv[c0 + 1]);
                float t2 = lrelu(f[2] + sbv[c0]);
                float t3 = lrelu(f[3] + sbv[c0 + 1]);
                v[0] += t0; v[1] += t1; v[2] += t2; v[3] += t3;
                *(uint32_t*)(vg + (size_t)r0 * E_N + c0)       = packh(t0, t1);
                *(uint32_t*)(vg + (size_t)(r0 + 8) * E_N + c0) = packh(t2, t3);
            }
        }
        __syncthreads();   // protect XH/WG overwrite next agent
    }

    // ---- Vsum -> gmem fp32 ----
    #pragma unroll
    for (int i = 0; i < 8; i++) {
        int r0 = warpM + (i >> 2) * 16 + (lane >> 2);
        int c0 = wn * 32 + (i & 3) * 8 + (lane & 3) * 2;
        float* v = vsum[i];
        *(float2*)(g_vsum + (size_t)(b0 + r0) * E_N + c0)     = make_float2(v[0], v[1]);
        *(float2*)(g_vsum + (size_t)(b0 + r0 + 8) * E_N + c0) = make_float2(v[2], v[3]);
    }
}

// ---------------- K2 smem layout ----------------
#define K2_XI   0
#define K2_WF1  (K2_XI  + 65536)
#define K2_BF1  (K2_WF1 + 65536)
#define K2_WF2  (K2_BF1 + 512)
#define K2_QP   (K2_WF2 + 512)
#define K2_SMEM (K2_QP  + 2048)   // 134656

// agent-outer mapping: blockIdx.x = a*64 + g; CTA loads Wf1[a] ONCE, sweeps 8 tiles.
#define K2_GROUPS 64
#define K2_TILES_PER_CTA (NTILES / K2_GROUPS)   // 8

__global__ void __launch_bounds__(NTHREADS, 1) k2_kernel(
    const float* __restrict__ Wf1, const float* __restrict__ bf1,
    const float* __restrict__ Wf2, const float* __restrict__ bf2,
    float* __restrict__ out)
{
    extern __shared__ char smem[];
    const uint32_t sb = smem_u32(smem);
    const int tid = threadIdx.x, wid = tid >> 5, lane = tid & 31;
    const int warpM = (wid >> 2) * 32, wn = wid & 3;
    const int a = blockIdx.x >> 6;           // agent
    const int grp = blockIdx.x & 63;         // tile group

    float* sbf1 = (float*)(smem + K2_BF1);
    float* swf2 = (float*)(smem + K2_WF2);
    float* qp   = (float*)(smem + K2_QP);

    // one-time: Wf1[a] B-tile (K=256), biases
    for (int it = 0; it < 8; it++) {
        int idx = tid + it * NTHREADS;          // 256*16 chunks
        int k = idx >> 4, c = idx & 15;
        const float* p = Wf1 + (size_t)a * 256 * E_N + (size_t)k * E_N + c * 8;
        *(uint4*)(smem + K2_WF1 + k * 256 + swz(c, k) * 16) = cvt8(p);
    }
    if (tid < 128) {
        sbf1[tid] = bf1[a * E_N + tid];
        swf2[tid] = Wf2[a * E_N + tid];
    }
    const float bf2a = bf2[a];
    __syncthreads();

    for (int ti = 0; ti < K2_TILES_PER_CTA; ti++) {
        const int b0 = (grp * K2_TILES_PER_CTA + ti) * BT;

        // ---- load e -> XI chunks 16..31 ; xi = Vsum - V -> XI chunks 0..15 ----
        {
            const __half* eg = g_e + ((size_t)a * B_N + b0) * E_N;
            const __half* vg = g_v + ((size_t)a * B_N + b0) * E_N;
            const float* vsg = g_vsum + (size_t)b0 * E_N;
            for (int it = 0; it < 4; it++) {
                int idx = tid + it * NTHREADS;    // 128*16 chunks
                int r = idx >> 4, c = idx & 15;
                uint4 ev = *(const uint4*)(eg + (size_t)r * E_N + c * 8);
                *(uint4*)(smem + K2_XI + r * 512 + swz(16 + c, r) * 16) = ev;

                uint4 vv = *(const uint4*)(vg + (size_t)r * E_N + c * 8);
                float4 s0 = *(const float4*)(vsg + (size_t)r * E_N + c * 8);
                float4 s1 = *(const float4*)(vsg + (size_t)r * E_N + c * 8 + 4);
                __half2* hp = (__half2*)&vv;
                float2 p0 = __half22float2(hp[0]);
                float2 p1 = __half22float2(hp[1]);
                float2 p2 = __half22float2(hp[2]);
                float2 p3 = __half22float2(hp[3]);
                uint4 xo = make_uint4(
                    packh(s0.x - p0.x, s0.y - p0.y),
                    packh(s0.z - p1.x, s0.w - p1.y),
                    packh(s1.x - p2.x, s1.y - p2.y),
                    packh(s1.z - p3.x, s1.w - p3.y));
                *(uint4*)(smem + K2_XI + r * 512 + swz(c, r) * 16) = xo;
            }
        }
        __syncthreads();

        // ---- GEMM-f1: H = [xi | e] @ Wf1 (K=256) ----
        float acc[8][4];
        ZERO_ACC8(acc);
        wgemm<16>(sb + K2_XI, 512, 0, sb + K2_WF1, warpM, wn, lane, acc);

        // ---- epilogue: qv = lrelu(H + bf1) . wf2 + bf2 (fp32) ----
        {
            float pr[2][2] = {{0.f, 0.f}, {0.f, 0.f}};
            #pragma unroll
            for (int i = 0; i < 8; i++) {
                int mi = i >> 2;
                int c0 = wn * 32 + (i & 3) * 8 + (lane & 3) * 2;
                float* f = acc[i];
                pr[mi][0] += lrelu(f[0] + sbf1[c0]) * swf2[c0]
                           + lrelu(f[1] + sbf1[c0 + 1]) * swf2[c0 + 1];
                pr[mi][1] += lrelu(f[2] + sbf1[c0]) * swf2[c0]
                           + lrelu(f[3] + sbf1[c0 + 1]) * swf2[c0 + 1];
            }
            #pragma unroll
            for (int off = 1; off <= 2; off <<= 1) {
                #pragma unroll
                for (int mi = 0; mi < 2; mi++) {
                    pr[mi][0] += __shfl_xor_sync(0xFFFFFFFF, pr[mi][0], off);
                    pr[mi][1] += __shfl_xor_sync(0xFFFFFFFF, pr[mi][1], off);
                }
            }
            if ((lane & 3) == 0) {
                #pragma unroll
                for (int mi = 0; mi < 2; mi++) {
                    int r0 = warpM + mi * 16 + (lane >> 2);
                    qp[r0 * 4 + wn]       = pr[mi][0];
                    qp[(r0 + 8) * 4 + wn] = pr[mi][1];
                }
            }
        }
        __syncthreads();
        if (tid < 128)
            out[(size_t)a * B_N + b0 + tid] =
                qp[tid * 4] + qp[tid * 4 + 1] + qp[tid * 4 + 2] + qp[tid * 4 + 3] + bf2a;
        __syncthreads();   // protect XI/qp overwrite next tile
    }
}

extern "C" void kernel_launch(void* const* d_in, const int* in_sizes, int n_in,
                              void* d_out, int out_size) {
    const float* obs = (const float*)d_in[0];
    const float* act = (const float*)d_in[1];
    const float* Wg  = (const float*)d_in[2];
    const float* bg  = (const float*)d_in[3];
    // d_in[4] = Wq, d_in[5] = Wk : dead code (softmax over singleton axis -> alpha == 1)
    const float* Wv  = (const float*)d_in[6];
    const float* bv  = (const float*)d_in[7];
    const float* Wf1 = (const float*)d_in[8];
    const float* bf1 = (const float*)d_in[9];
    const float* Wf2 = (const float*)d_in[10];
    const float* bf2 = (const float*)d_in[11];
    float* out = (float*)d_out;

    cudaFuncSetAttribute(k1_kernel, cudaFuncAttributeMaxDynamicSharedMemorySize, K1_SMEM);
    cudaFuncSetAttribute(k2_kernel, cudaFuncAttributeMaxDynamicSharedMemorySize, K2_SMEM);

    k1_kernel<<<NTILES, NTHREADS, K1_SMEM>>>(obs, act, Wg, bg, Wv, bv);
    k2_kernel<<<A_N * K2_GROUPS, NTHREADS, K2_SMEM>>>(Wf1, bf1, Wf2, bf2, out);
}

// round 8
// speedup vs baseline: 1.8867x; 1.1684x over previous
#include <cuda_runtime.h>
#include <cuda_fp16.h>
#include <cstdint>

#define A_N   8
#define B_N   65536
#define E_N   128
#define BT    128
#define NTILES 512

// ---- scratch: fp16 pre-swizzled tile images (__device__ globals: allowed) ----
__device__ __align__(16) unsigned char g_wgi[A_N * 160 * 256];              // 320 KB
__device__ __align__(16) unsigned char g_wvi[128 * 256];                    // 32 KB
__device__ __align__(16) unsigned char g_wf1i[A_N * 256 * 256];             // 512 KB
__device__ __align__(16) unsigned char g_ei[(size_t)A_N * NTILES * 32768];  // 128 MB
__device__ __align__(16) unsigned char g_vi[(size_t)A_N * NTILES * 32768];  // 128 MB
__device__ __align__(16) unsigned char g_vsi[(size_t)NTILES * 32768];       // 16 MB

// ---------------- helpers ----------------
__device__ __forceinline__ uint32_t smem_u32(const void* p) {
    uint32_t r;
    asm("{ .reg .u64 t; cvta.to.shared.u64 t, %1; cvt.u32.u64 %0, t; }" : "=r"(r) : "l"(p));
    return r;
}
__device__ __forceinline__ uint32_t packh(float a, float b) {
    __half2 h = __floats2half2_rn(a, b);
    return *(uint32_t*)&h;
}
__device__ __forceinline__ float lrelu(float x) { return x > 0.f ? x : 0.01f * x; }

__device__ __forceinline__ void cp16(uint32_t dst, const void* src) {
    asm volatile("cp.async.cg.shared.global [%0], [%1], 16;" :: "r"(dst), "l"(src));
}
#define CP_COMMIT() asm volatile("cp.async.commit_group;" ::: "memory")
#define CP_WAIT0()  asm volatile("cp.async.wait_group 0;" ::: "memory")

__device__ __forceinline__ void ldsm_x4(uint32_t* r, uint32_t addr) {
    asm volatile("ldmatrix.sync.aligned.m8n8.x4.shared.b16 {%0,%1,%2,%3}, [%4];"
        : "=r"(r[0]), "=r"(r[1]), "=r"(r[2]), "=r"(r[3]) : "r"(addr));
}
__device__ __forceinline__ void ldsm_x4t(uint32_t* r, uint32_t addr) {
    asm volatile("ldmatrix.sync.aligned.m8n8.x4.trans.shared.b16 {%0,%1,%2,%3}, [%4];"
        : "=r"(r[0]), "=r"(r[1]), "=r"(r[2]), "=r"(r[3]) : "r"(addr));
}
__device__ __forceinline__ void mma16816(float* d, const uint32_t* a, const uint32_t* b) {
    asm volatile("mma.sync.aligned.m16n8k16.row.col.f32.f16.f16.f32 "
        "{%0,%1,%2,%3}, {%4,%5,%6,%7}, {%8,%9}, {%0,%1,%2,%3};"
        : "+f"(d[0]), "+f"(d[1]), "+f"(d[2]), "+f"(d[3])
        : "r"(a[0]), "r"(a[1]), "r"(a[2]), "r"(a[3]), "r"(b[0]), "r"(b[1]));
}

// xor-swizzle 16B chunks within groups of 8 -> conflict-free ldmatrix
__device__ __forceinline__ int swz(int chunk, int row) {
    return (chunk & ~7) | ((chunk ^ row) & 7);
}

// generic warp GEMM. A tile rows stride aStride bytes (chunks from 0).
// B tile rows stride 256 bytes. Warp computes rows [warpM, +MI*16), col-chunks [wn*NJ*2, +NJ*2).
template<int NSTEPS, int MI, int NJ>
__device__ __forceinline__ void wgemm(uint32_t aBase, int aStride, uint32_t bBase,
                                      int warpM, int wn, int lane, float (*acc)[4])
{
    const int lr = lane & 15, lh = lane >> 4;
    #pragma unroll
    for (int ks = 0; ks < NSTEPS; ks++) {
        uint32_t afr[MI][4];
        #pragma unroll
        for (int mi = 0; mi < MI; mi++) {
            int row = warpM + mi * 16 + lr;
            ldsm_x4(afr[mi], aBase + row * aStride + swz(2 * ks + lh, row) * 16);
        }
        uint32_t bfr[NJ][4];
        #pragma unroll
        for (int nj = 0; nj < NJ; nj++) {
            int k = ks * 16 + lr;
            ldsm_x4t(bfr[nj], bBase + k * 256 + swz(wn * NJ * 2 + nj * 2 + lh, k) * 16);
        }
        #pragma unroll
        for (int mi = 0; mi < MI; mi++)
            #pragma unroll
            for (int nj = 0; nj < NJ; nj++) {
                mma16816(acc[(mi * NJ + nj) * 2],     afr[mi], &bfr[nj][0]);
                mma16816(acc[(mi * NJ + nj) * 2 + 1], afr[mi], &bfr[nj][2]);
            }
    }
}

#define ZERO_ACC8(acc) do { \
    _Pragma("unroll") for (int _i = 0; _i < 8; _i++) \
    _Pragma("unroll") for (int _j = 0; _j < 4; _j++) (acc)[_i][_j] = 0.f; \
} while (0)

__device__ __forceinline__ uint4 cvt8(const float* p) {
    float4 f0 = ((const float4*)p)[0];
    float4 f1 = ((const float4*)p)[1];
    return make_uint4(packh(f0.x, f0.y), packh(f0.z, f0.w),
                      packh(f1.x, f1.y), packh(f1.z, f1.w));
}
__device__ __forceinline__ uint4 cvt8r(uint4 a, uint4 b) {
    float* fa = (float*)&a; float* fb = (float*)&b;
    return make_uint4(packh(fa[0], fa[1]), packh(fa[2], fa[3]),
                      packh(fb[0], fb[1]), packh(fb[2], fb[3]));
}

// ---------------- K0: weight -> fp16 pre-swizzled images ----------------
__global__ void k0_kernel(const float* __restrict__ Wg, const float* __restrict__ Wv,
                          const float* __restrict__ Wf1)
{
    const int b = blockIdx.x, tid = threadIdx.x;
    if (b < A_N) {
        for (int i = tid; i < 2560; i += 256) {           // Wg[b]: 160 x 16 chunks
            int k = i >> 4, c = i & 15;
            *(uint4*)(g_wgi + b * 40960 + k * 256 + swz(c, k) * 16) =
                cvt8(Wg + ((size_t)b * 160 + k) * E_N + c * 8);
        }
        for (int i = tid; i < 4096; i += 256) {           // Wf1[b]: 256 x 16 chunks
            int k = i >> 4, c = i & 15;
            *(uint4*)(g_wf1i + b * 65536 + k * 256 + swz(c, k) * 16) =
                cvt8(Wf1 + ((size_t)b * 256 + k) * E_N + c * 8);
        }
    } else {
        for (int i = tid; i < 2048; i += 256) {           // Wv: 128 x 16 chunks, B[k][n=h*32+d]
            int k = i >> 4, c = i & 15;
            *(uint4*)(g_wvi + k * 256 + swz(c, k) * 16) =
                cvt8(Wv + (size_t)(c >> 2) * E_N * 32 + (size_t)k * 32 + (c & 3) * 8);
        }
    }
}

// ---------------- K1: e + V + Vsum (tile-outer, 512 CTAs x 512 thr) ----------------
#define K1_WG0  0
#define K1_WG1  40960
#define K1_WV   81920
#define K1_X    114688
#define K1_S    147456
#define K1_BG   212992
#define K1_BV   217088
#define K1_SMEM 217600

__global__ void __launch_bounds__(512, 1) k1_kernel(
    const float* __restrict__ obs, const float* __restrict__ act,
    const float* __restrict__ bg,  const float* __restrict__ bv)
{
    extern __shared__ char smem[];
    const uint32_t sb = smem_u32(smem);
    const int tid = threadIdx.x, wid = tid >> 5, lane = tid & 31;
    const int warpM = (wid >> 2) * 32, wn = wid & 3;
    const int b0 = blockIdx.x * BT;

    float* sbg = (float*)(smem + K1_BG);
    float* sbv = (float*)(smem + K1_BV);
    if (tid < 128) {
        sbv[tid] = bv[tid];
        #pragma unroll
        for (int a = 0; a < A_N; a++) sbg[a * 128 + tid] = bg[a * 128 + tid];
    }

    // prologue: cp.async Wv + Wg[0] + obs[0]; act[0] -> regs
    for (int i = tid; i < 2048; i += 512) cp16(sb + K1_WV  + i * 16, g_wvi + i * 16);
    for (int i = tid; i < 2560; i += 512) cp16(sb + K1_WG0 + i * 16, g_wgi + i * 16);
    {
        const char* op = (const char*)(obs + (size_t)b0 * 128);
        for (int i = tid; i < 4096; i += 512) cp16(sb + K1_S + i * 16, op + i * 16);
    }
    CP_COMMIT();
    uint4 actpf[2];
    {
        const char* ap = (const char*)(act + (size_t)b0 * 32);
        int r = tid >> 2, c = tid & 3;
        actpf[0] = *(const uint4*)(ap + r * 128 + c * 32);
        actpf[1] = *(const uint4*)(ap + r * 128 + c * 32 + 16);
    }

    float vsum[8][4];
    ZERO_ACC8(vsum);

    for (int a = 0; a < A_N; a++) {
        const uint32_t WGc = sb + ((a & 1) ? K1_WG1 : K1_WG0);
        const uint32_t WGn = sb + ((a & 1) ? K1_WG0 : K1_WG1);

        CP_WAIT0();
        __syncthreads();                       // S = obs[a] fp32, WGc = Wg[a]

        // cvt S -> X (obs chunks 0..15)
        #pragma unroll
        for (int it = 0; it < 4; it++) {
            int idx = tid + it * 512, r = idx >> 4, c = idx & 15;
            *(uint4*)(smem + K1_X + r * 256 + swz(c, r) * 16) =
                cvt8((const float*)(smem + K1_S + r * 512 + c * 32));
        }
        __syncthreads();                       // S free, X ready

        if (a < 7) {                           // prefetch obs[a+1], Wg[a+1]
            const char* on = (const char*)(obs + ((size_t)(a + 1) * B_N + b0) * 128);
            for (int i = tid; i < 4096; i += 512) cp16(sb + K1_S + i * 16, on + i * 16);
            for (int i = tid; i < 2560; i += 512) cp16(WGn + i * 16, g_wgi + (a + 1) * 40960 + i * 16);
        }
        CP_COMMIT();

        // GEMM1a: obs part (K=128)
        float acc[8][4];
        ZERO_ACC8(acc);
        wgemm<8, 2, 2>(sb + K1_X, 256, WGc, warpM, wn, lane, acc);
        __syncthreads();

        // act -> X chunks 0..3 (from regs); prefetch act[a+1]
        {
            int r = tid >> 2, c = tid & 3;
            *(uint4*)(smem + K1_X + r * 256 + swz(c, r) * 16) = cvt8r(actpf[0], actpf[1]);
        }
        if (a < 7) {
            const char* an = (const char*)(act + ((size_t)(a + 1) * B_N + b0) * 32);
            int r = tid >> 2, c = tid & 3;
            actpf[0] = *(const uint4*)(an + r * 128 + c * 32);
            actpf[1] = *(const uint4*)(an + r * 128 + c * 32 + 16);
        }
        __syncthreads();

        // GEMM1b: act part (K=32), Wg rows 128..159
        wgemm<2, 2, 2>(sb + K1_X, 256, WGc + 128 * 256, warpM, wn, lane, acc);
        __syncthreads();

        // epilogue: e = lrelu(.+bg) -> X chunks 0..15
        {
            const float* bga = sbg + a * 128;
            #pragma unroll
            for (int i = 0; i < 8; i++) {
                int r0 = warpM + (i >> 2) * 16 + (lane >> 2);
                int c0 = wn * 32 + (i & 3) * 8 + (lane & 3) * 2;
                float* f = acc[i];
                uint32_t lo = packh(lrelu(f[0] + bga[c0]), lrelu(f[1] + bga[c0 + 1]));
                uint32_t hi = packh(lrelu(f[2] + bga[c0]), lrelu(f[3] + bga[c0 + 1]));
                *(uint32_t*)(smem + K1_X + r0 * 256 + swz(c0 >> 3, r0) * 16 + (c0 & 7) * 2) = lo;
                int r1 = r0 + 8;
                *(uint32_t*)(smem + K1_X + r1 * 256 + swz(c0 >> 3, r1) * 16 + (c0 & 7) * 2) = hi;
            }
        }
        __syncthreads();

        // e image -> gmem (byte copy of smem tile), overlapped with GEMM2
        {
            unsigned char* eimg = g_ei + ((size_t)a * NTILES + blockIdx.x) * 32768;
            #pragma unroll
            for (int it = 0; it < 4; it++) {
                int i = tid + it * 512;
                *(uint4*)(eimg + i * 16) = *(const uint4*)(smem + K1_X + i * 16);
            }
        }

        // GEMM2: P = e @ Wv (K=128)
        ZERO_ACC8(acc);
        wgemm<8, 2, 2>(sb + K1_X, 256, sb + K1_WV, warpM, wn, lane, acc);

        // V = lrelu(P+bv); vsum += V; V image write
        {
            unsigned char* vimg = g_vi + ((size_t)a * NTILES + blockIdx.x) * 32768;
            #pragma unroll
            for (int i = 0; i < 8; i++) {
                int r0 = warpM + (i >> 2) * 16 + (lane >> 2);
                int c0 = wn * 32 + (i & 3) * 8 + (lane & 3) * 2;
                float* f = acc[i];
                float* v = vsum[i];
                float t0 = lrelu(f[0] + sbv[c0]);
                float t1 = lrelu(f[1] + sbv[c0 + 1]);
                float t2 = lrelu(f[2] + sbv[c0]);
                float t3 = lrelu(f[3] + sbv[c0 + 1]);
                v[0] += t0; v[1] += t1; v[2] += t2; v[3] += t3;
                *(uint32_t*)(vimg + r0 * 256 + swz(c0 >> 3, r0) * 16 + (c0 & 7) * 2) = packh(t0, t1);
                int r1 = r0 + 8;
                *(uint32_t*)(vimg + r1 * 256 + swz(c0 >> 3, r1) * 16 + (c0 & 7) * 2) = packh(t2, t3);
            }
        }
        // top-of-loop wait+sync protects X/S reuse
    }

    // Vsum -> fp16 image
    {
        unsigned char* vsimg = g_vsi + (size_t)blockIdx.x * 32768;
        #pragma unroll
        for (int i = 0; i < 8; i++) {
            int r0 = warpM + (i >> 2) * 16 + (lane >> 2);
            int c0 = wn * 32 + (i & 3) * 8 + (lane & 3) * 2;
            float* v = vsum[i];
            *(uint32_t*)(vsimg + r0 * 256 + swz(c0 >> 3, r0) * 16 + (c0 & 7) * 2) = packh(v[0], v[1]);
            int r1 = r0 + 8;
            *(uint32_t*)(vsimg + r1 * 256 + swz(c0 >> 3, r1) * 16 + (c0 & 7) * 2) = packh(v[2], v[3]);
        }
    }
}

// ---------------- K2: qv (agent-outer, 64-row tiles, 256 thr, 2 CTAs/SM) ----------------
#define K2_WF1  0
#define K2_X    65536
#define K2_BF1  81920
#define K2_WF2  82432
#define K2_QP   82944
#define K2_SMEM 83968
#define K2_TPC  16   // 64-row tiles per CTA

__global__ void __launch_bounds__(256, 2) k2_kernel(
    const float* __restrict__ bf1, const float* __restrict__ Wf2,
    const float* __restrict__ bf2, float* __restrict__ out)
{
    extern __shared__ char smem[];
    const uint32_t sb = smem_u32(smem);
    const int tid = threadIdx.x, wid = tid >> 5, lane = tid & 31;
    const int warpM = (wid >> 1) * 16, wn = wid & 1;
    const int a = blockIdx.x >> 6, grp = blockIdx.x & 63;

    float* sbf1 = (float*)(smem + K2_BF1);
    float* swf2 = (float*)(smem + K2_WF2);
    float* qp   = (float*)(smem + K2_QP);

    // WF1 image via cp.async; biases
    for (int i = tid; i < 4096; i += 256) cp16(sb + K2_WF1 + i * 16, g_wf1i + a * 65536 + i * 16);
    CP_COMMIT();
    if (tid < 128) { sbf1[tid] = bf1[a * 128 + tid]; swf2[tid] = Wf2[a * 128 + tid]; }
    const float bf2a = bf2[a];

    // prologue: e image for first 64-row tile
    const int tb0 = grp * K2_TPC;
    {
        const unsigned char* ei = g_ei + ((size_t)a * NTILES + (tb0 >> 1)) * 32768 + (size_t)(tb0 & 1) * 16384;
        for (int i = tid; i < 1024; i += 256) cp16(sb + K2_X + i * 16, ei + i * 16);
    }
    CP_COMMIT();

    for (int ti = 0; ti < K2_TPC; ti++) {
        const int tb = tb0 + ti;
        const int b0 = tb * 64;

        // V, Vsum halves -> regs (land during e-half GEMM)
        uint4 vv[4], vs[4];
        {
            const unsigned char* vimg  = g_vi  + ((size_t)a * NTILES + (tb >> 1)) * 32768 + (size_t)(tb & 1) * 16384;
            const unsigned char* vsimg = g_vsi + (size_t)(tb >> 1) * 32768 + (size_t)(tb & 1) * 16384;
            #pragma unroll
            for (int it = 0; it < 4; it++) {
                vv[it] = *(const uint4*)(vimg  + (tid + it * 256) * 16);
                vs[it] = *(const uint4*)(vsimg + (tid + it * 256) * 16);
            }
        }

        CP_WAIT0();
        __syncthreads();                           // X = e half-tile

        float acc[8][4];
        ZERO_ACC8(acc);
        // e-half: Wf1 rows 128..255
        wgemm<8, 1, 4>(sb + K2_X, 256, sb + K2_WF1 + 128 * 256, warpM, wn, lane, acc);
        __syncthreads();

        // xi = Vsum - V -> X (same image offsets => swizzle-consistent)
        #pragma unroll
        for (int it = 0; it < 4; it++) {
            uint4 x;
            __half2* pa = (__half2*)&vs[it];
            __half2* pb = (__half2*)&vv[it];
            __half2* po = (__half2*)&x;
            #pragma unroll
            for (int j = 0; j < 4; j++) po[j] = __hsub2(pa[j], pb[j]);
            *(uint4*)(smem + K2_X + (tid + it * 256) * 16) = x;
        }
        __syncthreads();

        // xi-half: Wf1 rows 0..127
        wgemm<8, 1, 4>(sb + K2_X, 256, sb + K2_WF1, warpM, wn, lane, acc);
        __syncthreads();

        // prefetch next tile's e image into X (lands during epilogue + next top)
        if (ti + 1 < K2_TPC) {
            int tn = tb + 1;
            const unsigned char* ei = g_ei + ((size_t)a * NTILES + (tn >> 1)) * 32768 + (size_t)(tn & 1) * 16384;
            for (int i = tid; i < 1024; i += 256) cp16(sb + K2_X + i * 16, ei + i * 16);
        }
        CP_COMMIT();

        // epilogue: qv = lrelu(H + bf1) . wf2 + bf2
        {
            float pr0 = 0.f, pr1 = 0.f;
            #pragma unroll
            for (int i = 0; i < 8; i++) {
                int c0 = wn * 64 + i * 8 + (lane & 3) * 2;
                float* f = acc[i];
                pr0 += lrelu(f[0] + sbf1[c0]) * swf2[c0]
                     + lrelu(f[1] + sbf1[c0 + 1]) * swf2[c0 + 1];
                pr1 += lrelu(f[2] + sbf1[c0]) * swf2[c0]
                     + lrelu(f[3] + sbf1[c0 + 1]) * swf2[c0 + 1];
            }
            #pragma unroll
            for (int off = 1; off <= 2; off <<= 1) {
                pr0 += __shfl_xor_sync(0xFFFFFFFF, pr0, off);
                pr1 += __shfl_xor_sync(0xFFFFFFFF, pr1, off);
            }
            if ((lane & 3) == 0) {
                int r0 = warpM + (lane >> 2);
                qp[r0 * 2 + wn]       = pr0;
                qp[(r0 + 8) * 2 + wn] = pr1;
            }
        }
        __syncthreads();
        if (tid < 64)
            out[(size_t)a * B_N + b0 + tid] = qp[tid * 2] + qp[tid * 2 + 1] + bf2a;
        // qp next written only after >=2 syncs of next tile -> safe
    }
}

extern "C" void kernel_launch(void* const* d_in, const int* in_sizes, int n_in,
                              void* d_out, int out_size) {
    const float* obs = (const float*)d_in[0];
    const float* act = (const float*)d_in[1];
    const float* Wg  = (const float*)d_in[2];
    const float* bg  = (const float*)d_in[3];
    // d_in[4] = Wq, d_in[5] = Wk : dead code (softmax over singleton axis -> alpha == 1)
    const float* Wv  = (const float*)d_in[6];
    const float* bv  = (const float*)d_in[7];
    const float* Wf1 = (const float*)d_in[8];
    const float* bf1 = (const float*)d_in[9];
    const float* Wf2 = (const float*)d_in[10];
    const float* bf2 = (const float*)d_in[11];
    float* out = (float*)d_out;

    cudaFuncSetAttribute(k1_kernel, cudaFuncAttributeMaxDynamicSharedMemorySize, K1_SMEM);
    cudaFuncSetAttribute(k2_kernel, cudaFuncAttributeMaxDynamicSharedMemorySize, K2_SMEM);

    k0_kernel<<<A_N + 1, 256>>>(Wg, Wv, Wf1);
    k1_kernel<<<NTILES, 512, K1_SMEM>>>(obs, act, bg, bv);
    k2_kernel<<<A_N * 64, 256, K2_SMEM>>>(bf1, Wf2, bf2, out);
}

// round 10
// speedup vs baseline: 1.9645x; 1.0412x over previous
#include <cuda_runtime.h>
#include <cuda_fp16.h>
#include <cstdint>

#define A_N   8
#define B_N   65536
#define E_N   128
#define BT    128
#define NTILES 512

// ---- scratch: fp16 pre-swizzled tile images (__device__ globals: allowed) ----
__device__ __align__(16) unsigned char g_wgi[A_N * 160 * 256];              // 320 KB
__device__ __align__(16) unsigned char g_wvi[128 * 256];                    // 32 KB
__device__ __align__(16) unsigned char g_wf1i[A_N * 256 * 256];             // 512 KB
__device__ __align__(16) unsigned char g_ei[(size_t)A_N * NTILES * 32768];  // 128 MB
__device__ __align__(16) unsigned char g_vi[(size_t)A_N * NTILES * 32768];  // 128 MB
__device__ __align__(16) unsigned char g_vsi[(size_t)NTILES * 32768];       // 16 MB

// ---------------- helpers ----------------
__device__ __forceinline__ uint32_t smem_u32(const void* p) {
    uint32_t r;
    asm("{ .reg .u64 t; cvta.to.shared.u64 t, %1; cvt.u32.u64 %0, t; }" : "=r"(r) : "l"(p));
    return r;
}
__device__ __forceinline__ uint32_t packh(float a, float b) {
    __half2 h = __floats2half2_rn(a, b);
    return *(uint32_t*)&h;
}
__device__ __forceinline__ float lrelu(float x) { return x > 0.f ? x : 0.01f * x; }

__device__ __forceinline__ void cp16(uint32_t dst, const void* src) {
    asm volatile("cp.async.cg.shared.global [%0], [%1], 16;" :: "r"(dst), "l"(src));
}
#define CP_COMMIT() asm volatile("cp.async.commit_group;" ::: "memory")
#define CP_WAIT0()  asm volatile("cp.async.wait_group 0;" ::: "memory")

__device__ __forceinline__ void ldsm_x4(uint32_t* r, uint32_t addr) {
    asm volatile("ldmatrix.sync.aligned.m8n8.x4.shared.b16 {%0,%1,%2,%3}, [%4];"
        : "=r"(r[0]), "=r"(r[1]), "=r"(r[2]), "=r"(r[3]) : "r"(addr));
}
__device__ __forceinline__ void ldsm_x4t(uint32_t* r, uint32_t addr) {
    asm volatile("ldmatrix.sync.aligned.m8n8.x4.trans.shared.b16 {%0,%1,%2,%3}, [%4];"
        : "=r"(r[0]), "=r"(r[1]), "=r"(r[2]), "=r"(r[3]) : "r"(addr));
}
__device__ __forceinline__ void mma16816(float* d, const uint32_t* a, const uint32_t* b) {
    asm volatile("mma.sync.aligned.m16n8k16.row.col.f32.f16.f16.f32 "
        "{%0,%1,%2,%3}, {%4,%5,%6,%7}, {%8,%9}, {%0,%1,%2,%3};"
        : "+f"(d[0]), "+f"(d[1]), "+f"(d[2]), "+f"(d[3])
        : "r"(a[0]), "r"(a[1]), "r"(a[2]), "r"(a[3]), "r"(b[0]), "r"(b[1]));
}

// xor-swizzle 16B chunks within groups of 8 -> conflict-free ldmatrix
__device__ __forceinline__ int swz(int chunk, int row) {
    return (chunk & ~7) | ((chunk ^ row) & 7);
}

// generic warp GEMM. A tile rows stride aStride bytes (chunks from 0).
// B tile rows stride 256 bytes. Warp computes rows [warpM, +MI*16), col-chunks [wn*NJ*2, +NJ*2).
template<int NSTEPS, int MI, int NJ>
__device__ __forceinline__ void wgemm(uint32_t aBase, int aStride, uint32_t bBase,
                                      int warpM, int wn, int lane, float (*acc)[4])
{
    const int lr = lane & 15, lh = lane >> 4;
    #pragma unroll
    for (int ks = 0; ks < NSTEPS; ks++) {
        uint32_t afr[MI][4];
        #pragma unroll
        for (int mi = 0; mi < MI; mi++) {
            int row = warpM + mi * 16 + lr;
            ldsm_x4(afr[mi], aBase + row * aStride + swz(2 * ks + lh, row) * 16);
        }
        uint32_t bfr[NJ][4];
        #pragma unroll
        for (int nj = 0; nj < NJ; nj++) {
            int k = ks * 16 + lr;
            ldsm_x4t(bfr[nj], bBase + k * 256 + swz(wn * NJ * 2 + nj * 2 + lh, k) * 16);
        }
        #pragma unroll
        for (int mi = 0; mi < MI; mi++)
            #pragma unroll
            for (int nj = 0; nj < NJ; nj++) {
                mma16816(acc[(mi * NJ + nj) * 2],     afr[mi], &bfr[nj][0]);
                mma16816(acc[(mi * NJ + nj) * 2 + 1], afr[mi], &bfr[nj][2]);
            }
    }
}

#define ZERO_ACC8(acc) do { \
    _Pragma("unroll") for (int _i = 0; _i < 8; _i++) \
    _Pragma("unroll") for (int _j = 0; _j < 4; _j++) (acc)[_i][_j] = 0.f; \
} while (0)

__device__ __forceinline__ uint4 cvt8(const float* p) {
    float4 f0 = ((const float4*)p)[0];
    float4 f1 = ((const float4*)p)[1];
    return make_uint4(packh(f0.x, f0.y), packh(f0.z, f0.w),
                      packh(f1.x, f1.y), packh(f1.z, f1.w));
}
__device__ __forceinline__ uint4 cvt8r(uint4 a, uint4 b) {
    float* fa = (float*)&a; float* fb = (float*)&b;
    return make_uint4(packh(fa[0], fa[1]), packh(fa[2], fa[3]),
                      packh(fb[0], fb[1]), packh(fb[2], fb[3]));
}

// ---------------- K0: weight -> fp16 pre-swizzled images (flat, full-chip) ----------------
// elements: Wg 8*2560=20480, Wf1 8*4096=32768, Wv 2048 -> 55296 uint4 ops; grid 108 x 512.
__global__ void __launch_bounds__(512) k0_kernel(
    const float* __restrict__ Wg, const float* __restrict__ Wv,
    const float* __restrict__ Wf1)
{
    int idx = blockIdx.x * 512 + threadIdx.x;
    if (idx < 20480) {
        int b = idx / 2560, i = idx % 2560;
        int k = i >> 4, c = i & 15;
        *(uint4*)(g_wgi + b * 40960 + k * 256 + swz(c, k) * 16) =
            cvt8(Wg + ((size_t)b * 160 + k) * E_N + c * 8);
    } else if (idx < 53248) {
        int j = idx - 20480;
        int b = j >> 12, i = j & 4095;
        int k = i >> 4, c = i & 15;
        *(uint4*)(g_wf1i + b * 65536 + k * 256 + swz(c, k) * 16) =
            cvt8(Wf1 + ((size_t)b * 256 + k) * E_N + c * 8);
    } else if (idx < 55296) {
        int i = idx - 53248;
        int k = i >> 4, c = i & 15;
        *(uint4*)(g_wvi + k * 256 + swz(c, k) * 16) =
            cvt8(Wv + (size_t)(c >> 2) * E_N * 32 + (size_t)k * 32 + (c & 3) * 8);
    }
}

// ---------------- K1: e + V + Vsum (tile-outer, 512 CTAs x 512 thr) ----------------
// X: [128 rows][24-chunk stride 384B]; obs fp16 -> chunks 0..15, act -> chunks 16..19.
#define K1_WG   0
#define K1_WV   40960
#define K1_X    73728
#define K1_S    122880
#define K1_BG   188416
#define K1_BV   192512
#define K1_SMEM 193024

__global__ void __launch_bounds__(512, 1) k1_kernel(
    const float* __restrict__ obs, const float* __restrict__ act,
    const float* __restrict__ bg,  const float* __restrict__ bv)
{
    extern __shared__ char smem[];
    const uint32_t sb = smem_u32(smem);
    const int tid = threadIdx.x, wid = tid >> 5, lane = tid & 31;
    const int warpM = (wid >> 2) * 32, wn = wid & 3;
    const int b0 = blockIdx.x * BT;

    float* sbg = (float*)(smem + K1_BG);
    float* sbv = (float*)(smem + K1_BV);
    if (tid < 128) {
        sbv[tid] = bv[tid];
        #pragma unroll
        for (int a = 0; a < A_N; a++) sbg[a * 128 + tid] = bg[a * 128 + tid];
    }

    // prologue: cp.async Wv + Wg[0] + obs[0]; act[0] -> regs
    for (int i = tid; i < 2048; i += 512) cp16(sb + K1_WV + i * 16, g_wvi + i * 16);
    for (int i = tid; i < 2560; i += 512) cp16(sb + K1_WG + i * 16, g_wgi + i * 16);
    {
        const char* op = (const char*)(obs + (size_t)b0 * 128);
        for (int i = tid; i < 4096; i += 512) cp16(sb + K1_S + i * 16, op + i * 16);
    }
    CP_COMMIT();
    uint4 actpf[2];
    {
        const char* ap = (const char*)(act + (size_t)b0 * 32);
        int r = tid >> 2, c = tid & 3;
        actpf[0] = *(const uint4*)(ap + r * 128 + c * 32);
        actpf[1] = *(const uint4*)(ap + r * 128 + c * 32 + 16);
    }

    float vsum[8][4];
    ZERO_ACC8(vsum);

    for (int a = 0; a < A_N; a++) {
        CP_WAIT0();
        __syncthreads();                       // S = obs[a] fp32, WG = Wg[a]

        // cvt S -> X chunks 0..15 ; act regs -> X chunks 16..19 ; refresh actpf
        #pragma unroll
        for (int it = 0; it < 4; it++) {
            int idx = tid + it * 512, r = idx >> 4, c = idx & 15;
            *(uint4*)(smem + K1_X + r * 384 + swz(c, r) * 16) =
                cvt8((const float*)(smem + K1_S + r * 512 + c * 32));
        }
        {
            int r = tid >> 2, c = tid & 3;
            *(uint4*)(smem + K1_X + r * 384 + swz(16 + c, r) * 16) = cvt8r(actpf[0], actpf[1]);
        }
        if (a < 7) {
            const char* an = (const char*)(act + ((size_t)(a + 1) * B_N + b0) * 32);
            int r = tid >> 2, c = tid & 3;
            actpf[0] = *(const uint4*)(an + r * 128 + c * 32);
            actpf[1] = *(const uint4*)(an + r * 128 + c * 32 + 16);
        }
        __syncthreads();                       // X ready, S free

        if (a < 7) {                           // prefetch obs[a+1] into S
            const char* on = (const char*)(obs + ((size_t)(a + 1) * B_N + b0) * 128);
            for (int i = tid; i < 4096; i += 512) cp16(sb + K1_S + i * 16, on + i * 16);
            CP_COMMIT();
        }

        // GEMM1: e_pre = x @ Wg (K=160, single pass)
        float acc[8][4];
        ZERO_ACC8(acc);
        wgemm<10, 2, 2>(sb + K1_X, 384, sb + K1_WG, warpM, wn, lane, acc);
        __syncthreads();                       // WG free; all warps done reading X

        if (a < 7) {                           // prefetch Wg[a+1] into WG (lands during epi+GEMM2)
            for (int i = tid; i < 2560; i += 512) cp16(sb + K1_WG + i * 16, g_wgi + (a + 1) * 40960 + i * 16);
            CP_COMMIT();
        }

        // epilogue: e = lrelu(.+bg) -> X chunks 0..15
        {
            const float* bga = sbg + a * 128;
            #pragma unroll
            for (int i = 0; i < 8; i++) {
                int r0 = warpM + (i >> 2) * 16 + (lane >> 2);
                int c0 = wn * 32 + (i & 3) * 8 + (lane & 3) * 2;
                float* f = acc[i];
                uint32_t lo = packh(lrelu(f[0] + bga[c0]), lrelu(f[1] + bga[c0 + 1]));
                uint32_t hi = packh(lrelu(f[2] + bga[c0]), lrelu(f[3] + bga[c0 + 1]));
                *(uint32_t*)(smem + K1_X + r0 * 384 + swz(c0 >> 3, r0) * 16 + (c0 & 7) * 2) = lo;
                int r1 = r0 + 8;
                *(uint32_t*)(smem + K1_X + r1 * 384 + swz(c0 >> 3, r1) * 16 + (c0 & 7) * 2) = hi;
            }
        }
        __syncthreads();

        // e image -> gmem (stride-384 X -> stride-256 image), overlapped with GEMM2
        {
            unsigned char* eimg = g_ei + ((size_t)a * NTILES + blockIdx.x) * 32768;
            #pragma unroll
            for (int it = 0; it < 4; it++) {
                int idx = tid + it * 512, r = idx >> 4, c = idx & 15;
                int o = swz(c, r) * 16;
                *(uint4*)(eimg + r * 256 + o) = *(const uint4*)(smem + K1_X + r * 384 + o);
            }
        }

        // GEMM2: P = e @ Wv (K=128)
        ZERO_ACC8(acc);
        wgemm<8, 2, 2>(sb + K1_X, 384, sb + K1_WV, warpM, wn, lane, acc);

        // V = lrelu(P+bv); vsum += V; V image write
        {
            unsigned char* vimg = g_vi + ((size_t)a * NTILES + blockIdx.x) * 32768;
            #pragma unroll
            for (int i = 0; i < 8; i++) {
                int r0 = warpM + (i >> 2) * 16 + (lane >> 2);
                int c0 = wn * 32 + (i & 3) * 8 + (lane & 3) * 2;
                float* f = acc[i];
                float* v = vsum[i];
                float t0 = lrelu(f[0] + sbv[c0]);
                float t1 = lrelu(f[1] + sbv[c0 + 1]);
                float t2 = lrelu(f[2] + sbv[c0]);
                float t3 = lrelu(f[3] + sbv[c0 + 1]);
                v[0] += t0; v[1] += t1; v[2] += t2; v[3] += t3;
                *(uint32_t*)(vimg + r0 * 256 + swz(c0 >> 3, r0) * 16 + (c0 & 7) * 2) = packh(t0, t1);
                int r1 = r0 + 8;
                *(uint32_t*)(vimg + r1 * 256 + swz(c0 >> 3, r1) * 16 + (c0 & 7) * 2) = packh(t2, t3);
            }
        }
        // top-of-loop wait+sync protects X/S/WG reuse
    }

    // Vsum -> fp16 image
    {
        unsigned char* vsimg = g_vsi + (size_t)blockIdx.x * 32768;
        #pragma unroll
        for (int i = 0; i < 8; i++) {
            int r0 = warpM + (i >> 2) * 16 + (lane >> 2);
            int c0 = wn * 32 + (i & 3) * 8 + (lane & 3) * 2;
            float* v = vsum[i];
            *(uint32_t*)(vsimg + r0 * 256 + swz(c0 >> 3, r0) * 16 + (c0 & 7) * 2) = packh(v[0], v[1]);
            int r1 = r0 + 8;
            *(uint32_t*)(vsimg + r1 * 256 + swz(c0 >> 3, r1) * 16 + (c0 & 7) * 2) = packh(v[2], v[3]);
        }
    }
}

// ---------------- K2: qv (agent-outer, 64-row tiles, 256 thr, 2 CTAs/SM) ----------------
#define K2_WF1  0
#define K2_X    65536
#define K2_BF1  81920
#define K2_WF2  82432
#define K2_QP   82944
#define K2_SMEM 83968
#define K2_TPC  16   // 64-row tiles per CTA

__global__ void __launch_bounds__(256, 2) k2_kernel(
    const float* __restrict__ bf1, const float* __restrict__ Wf2,
    const float* __restrict__ bf2, float* __restrict__ out)
{
    extern __shared__ char smem[];
    const uint32_t sb = smem_u32(smem);
    const int tid = threadIdx.x, wid = tid >> 5, lane = tid & 31;
    const int warpM = (wid >> 1) * 16, wn = wid & 1;
    const int a = blockIdx.x >> 6, grp = blockIdx.x & 63;

    float* sbf1 = (float*)(smem + K2_BF1);
    float* swf2 = (float*)(smem + K2_WF2);
    float* qp   = (float*)(smem + K2_QP);

    // WF1 image via cp.async; biases
    for (int i = tid; i < 4096; i += 256) cp16(sb + K2_WF1 + i * 16, g_wf1i + a * 65536 + i * 16);
    CP_COMMIT();
    if (tid < 128) { sbf1[tid] = bf1[a * 128 + tid]; swf2[tid] = Wf2[a * 128 + tid]; }
    const float bf2a = bf2[a];

    // prologue: e image for first 64-row tile
    const int tb0 = grp * K2_TPC;
    {
        const unsigned char* ei = g_ei + ((size_t)a * NTILES + (tb0 >> 1)) * 32768 + (size_t)(tb0 & 1) * 16384;
        for (int i = tid; i < 1024; i += 256) cp16(sb + K2_X + i * 16, ei + i * 16);
    }
    CP_COMMIT();

    for (int ti = 0; ti < K2_TPC; ti++) {
        const int tb = tb0 + ti;
        const int b0 = tb * 64;

        // V, Vsum halves -> regs (land during e-half GEMM)
        uint4 vv[4], vs[4];
        {
            const unsigned char* vimg  = g_vi  + ((size_t)a * NTILES + (tb >> 1)) * 32768 + (size_t)(tb & 1) * 16384;
            const unsigned char* vsimg = g_vsi + (size_t)(tb >> 1) * 32768 + (size_t)(tb & 1) * 16384;
            #pragma unroll
            for (int it = 0; it < 4; it++) {
                vv[it] = *(const uint4*)(vimg  + (tid + it * 256) * 16);
                vs[it] = *(const uint4*)(vsimg + (tid + it * 256) * 16);
            }
        }

        CP_WAIT0();
        __syncthreads();                           // X = e half-tile

        float acc[8][4];
        ZERO_ACC8(acc);
        // e-half: Wf1 rows 128..255
        wgemm<8, 1, 4>(sb + K2_X, 256, sb + K2_WF1 + 128 * 256, warpM, wn, lane, acc);
        __syncthreads();

        // xi = Vsum - V -> X (same image offsets => swizzle-consistent)
        #pragma unroll
        for (int it = 0; it < 4; it++) {
            uint4 x;
            __half2* pa = (__half2*)&vs[it];
            __half2* pb = (__half2*)&vv[it];
            __half2* po = (__half2*)&x;
            #pragma unroll
            for (int j = 0; j < 4; j++) po[j] = __hsub2(pa[j], pb[j]);
            *(uint4*)(smem + K2_X + (tid + it * 256) * 16) = x;
        }
        __syncthreads();

        // xi-half: Wf1 rows 0..127
        wgemm<8, 1, 4>(sb + K2_X, 256, sb + K2_WF1, warpM, wn, lane, acc);
        __syncthreads();

        // prefetch next tile's e image into X (lands during epilogue + next top)
        if (ti + 1 < K2_TPC) {
            int tn = tb + 1;
            const unsigned char* ei = g_ei + ((size_t)a * NTILES + (tn >> 1)) * 32768 + (size_t)(tn & 1) * 16384;
            for (int i = tid; i < 1024; i += 256) cp16(sb + K2_X + i * 16, ei + i * 16);
        }
        CP_COMMIT();

        // epilogue: qv = lrelu(H + bf1) . wf2 + bf2
        {
            float pr0 = 0.f, pr1 = 0.f;
            #pragma unroll
            for (int i = 0; i < 8; i++) {
                int c0 = wn * 64 + i * 8 + (lane & 3) * 2;
                float* f = acc[i];
                pr0 += lrelu(f[0] + sbf1[c0]) * swf2[c0]
                     + lrelu(f[1] + sbf1[c0 + 1]) * swf2[c0 + 1];
                pr1 += lrelu(f[2] + sbf1[c0]) * swf2[c0]
                     + lrelu(f[3] + sbf1[c0 + 1]) * swf2[c0 + 1];
            }
            #pragma unroll
            for (int off = 1; off <= 2; off <<= 1) {
                pr0 += __shfl_xor_sync(0xFFFFFFFF, pr0, off);
                pr1 += __shfl_xor_sync(0xFFFFFFFF, pr1, off);
            }
            if ((lane & 3) == 0) {
                int r0 = warpM + (lane >> 2);
                qp[r0 * 2 + wn]       = pr0;
                qp[(r0 + 8) * 2 + wn] = pr1;
            }
        }
        __syncthreads();
        if (tid < 64)
            out[(size_t)a * B_N + b0 + tid] = qp[tid * 2] + qp[tid * 2 + 1] + bf2a;
        // qp next written only after >=2 syncs of next tile -> safe
    }
}

extern "C" void kernel_launch(void* const* d_in, const int* in_sizes, int n_in,
                              void* d_out, int out_size) {
    const float* obs = (const float*)d_in[0];
    const float* act = (const float*)d_in[1];
    const float* Wg  = (const float*)d_in[2];
    const float* bg  = (const float*)d_in[3];
    // d_in[4] = Wq, d_in[5] = Wk : dead code (softmax over singleton axis -> alpha == 1)
    const float* Wv  = (const float*)d_in[6];
    const float* bv  = (const float*)d_in[7];
    const float* Wf1 = (const float*)d_in[8];
    const float* bf1 = (const float*)d_in[9];
    const float* Wf2 = (const float*)d_in[10];
    const float* bf2 = (const float*)d_in[11];
    float* out = (float*)d_out;

    cudaFuncSetAttribute(k1_kernel, cudaFuncAttributeMaxDynamicSharedMemorySize, K1_SMEM);
    cudaFuncSetAttribute(k2_kernel, cudaFuncAttributeMaxDynamicSharedMemorySize, K2_SMEM);

    k0_kernel<<<108, 512>>>(Wg, Wv, Wf1);
    k1_kernel<<<NTILES, 512, K1_SMEM>>>(obs, act, bg, bv);
    k2_kernel<<<A_N * 64, 256, K2_SMEM>>>(bf1, Wf2, bf2, out);
}